// round 1
// baseline (speedup 1.0000x reference)
#include <cuda_runtime.h>
#include <math.h>

#define B_   2
#define S_   2048
#define D_   2048
#define H_   8
#define HD_  256
#define WIN_ 1024

// Scratch (no allocations allowed)
__device__ float g_q[B_*S_*H_*HD_];      // [B,S,H*HD] = QKV-proj Q output, RoPE'd in place
__device__ float g_k[B_*S_*HD_];         // [B,S,HD]
__device__ float g_v[B_*S_*HD_];
__device__ float g_attn[B_*S_*H_*HD_];   // attention output before O-proj

// ---------------------------------------------------------------------------
// SGEMM (NT): C[M,N] = A[M,K] * B[N,K]^T, all row-major, K contiguous.
// 128x128 block tile, BK=16, 256 threads, 8x8 micro-tile per thread with
// interleaved ownership (rows ti+16*i, cols ci+16*j) -> conflict-free LDS.
// ---------------------------------------------------------------------------
__global__ void __launch_bounds__(256) sgemm_nt(const float* __restrict__ A,
                                                const float* __restrict__ Bm,
                                                float* __restrict__ C,
                                                int M, int N, int K)
{
    __shared__ float As[16][128];
    __shared__ float Bs[16][128];
    int tid = threadIdx.x;
    int ti = tid >> 4, ci = tid & 15;
    int m0 = blockIdx.y << 7, n0 = blockIdx.x << 7;

    float acc[8][8];
    #pragma unroll
    for (int i = 0; i < 8; i++)
        #pragma unroll
        for (int j = 0; j < 8; j++) acc[i][j] = 0.f;

    for (int kt = 0; kt < K; kt += 16) {
        #pragma unroll
        for (int l = 0; l < 2; l++) {
            int idx = tid + (l << 8);          // 0..511 (float4 index)
            int row = idx >> 2;                // 0..127
            int kq  = (idx & 3) << 2;          // 0,4,8,12
            float4 va = *(const float4*)(A + (size_t)(m0 + row) * K + kt + kq);
            As[kq+0][row] = va.x; As[kq+1][row] = va.y;
            As[kq+2][row] = va.z; As[kq+3][row] = va.w;
            float4 vb = *(const float4*)(Bm + (size_t)(n0 + row) * K + kt + kq);
            Bs[kq+0][row] = vb.x; Bs[kq+1][row] = vb.y;
            Bs[kq+2][row] = vb.z; Bs[kq+3][row] = vb.w;
        }
        __syncthreads();
        #pragma unroll
        for (int k = 0; k < 16; k++) {
            float a[8], b[8];
            #pragma unroll
            for (int i = 0; i < 8; i++) a[i] = As[k][ti + (i << 4)];
            #pragma unroll
            for (int j = 0; j < 8; j++) b[j] = Bs[k][ci + (j << 4)];
            #pragma unroll
            for (int i = 0; i < 8; i++)
                #pragma unroll
                for (int j = 0; j < 8; j++) acc[i][j] += a[i] * b[j];
        }
        __syncthreads();
    }

    #pragma unroll
    for (int i = 0; i < 8; i++) {
        int row = m0 + ti + (i << 4);
        #pragma unroll
        for (int j = 0; j < 8; j++)
            C[(size_t)row * N + n0 + ci + (j << 4)] = acc[i][j];
    }
}

// ---------------------------------------------------------------------------
// RoPE applied in place to g_q (8 heads) and g_k (1 head).
// One block per (b,s), 128 threads (one per rotation pair).
// ---------------------------------------------------------------------------
__global__ void rope_kernel(const int* __restrict__ pos_ids)
{
    int bs = blockIdx.x;           // 0..B*S-1
    int i  = threadIdx.x;          // 0..127
    float pos  = (float)pos_ids[bs];
    float expo = (float)(2 * i) / (float)HD_;
    float inv  = powf(10000.0f, -expo);
    float ang  = pos * inv;
    float c = cosf(ang), s = sinf(ang);

    int qbase = bs * (H_ * HD_);
    #pragma unroll
    for (int h = 0; h < H_; h++) {
        float x1 = g_q[qbase + h*HD_ + i];
        float x2 = g_q[qbase + h*HD_ + 128 + i];
        g_q[qbase + h*HD_ + i]       = x1 * c - x2 * s;
        g_q[qbase + h*HD_ + 128 + i] = x2 * c + x1 * s;
    }
    int kbase = bs * HD_;
    float y1 = g_k[kbase + i], y2 = g_k[kbase + 128 + i];
    g_k[kbase + i]       = y1 * c - y2 * s;
    g_k[kbase + 128 + i] = y2 * c + y1 * s;
}

// ---------------------------------------------------------------------------
// Flash attention with sliding-window causal mask.
// Grid: (S/32, B*H). Block: 256 threads.
// Thread (r = tid>>3, sub = tid&7): query row r; score keys kk = sub+8*j;
// output dims d = sub + 8*dd (interleaved -> conflict-free V reads).
// smem rows padded to 257 floats (stride%32==1 -> conflict-free).
// ---------------------------------------------------------------------------
__global__ void __launch_bounds__(256) attn_kernel()
{
    extern __shared__ float sm[];
    float* Qs = sm;                 // 32 x 257
    float* Ks = sm + 32*257;        // 32 x 257
    float* Vs = sm + 2*32*257;      // 32 x 257
    float* Ps = sm + 3*32*257;      // 32 x 33

    int tid = threadIdx.x;
    int r = tid >> 3, sub = tid & 7;
    int bh = blockIdx.y;
    int b = bh >> 3, h = bh & 7;
    int q0 = blockIdx.x << 5;
    int q  = q0 + r;
    const float scale = 0.0625f;    // 1/sqrt(256)

    // Load + pre-scale Q tile
    for (int i = tid; i < 32 * HD_; i += 256) {
        int row = i >> 8, col = i & 255;
        Qs[row*257 + col] =
            g_q[((b*S_ + q0 + row) * H_ + h) * HD_ + col] * scale;
    }

    float acc[32];
    #pragma unroll
    for (int d = 0; d < 32; d++) acc[d] = 0.f;
    float m = -INFINITY, l = 0.f;

    int kbeg = q0 - (WIN_ - 1);
    if (kbeg < 0) kbeg = 0;
    kbeg &= ~31;

    for (int kt = kbeg; kt <= q0; kt += 32) {
        __syncthreads();   // all warps done with previous K/V tiles
        for (int i = tid; i < 32 * HD_; i += 256) {
            int row = i >> 8, col = i & 255;
            int gk = (b*S_ + kt + row) * HD_ + col;
            Ks[row*257 + col] = g_k[gk];
            Vs[row*257 + col] = g_v[gk];
        }
        __syncthreads();

        // ---- scores: this thread does keys kt + sub + 8*{0,1,2,3}
        float s0 = 0.f, s1 = 0.f, s2 = 0.f, s3 = 0.f;
        {
            const float* qrow = Qs + r*257;
            const float* k0 = Ks + (sub     ) * 257;
            const float* k1 = Ks + (sub +  8) * 257;
            const float* k2 = Ks + (sub + 16) * 257;
            const float* k3 = Ks + (sub + 24) * 257;
            #pragma unroll 8
            for (int d = 0; d < HD_; d++) {
                float qd = qrow[d];
                s0 += qd * k0[d];
                s1 += qd * k1[d];
                s2 += qd * k2[d];
                s3 += qd * k3[d];
            }
        }
        float sc[4] = {s0, s1, s2, s3};
        #pragma unroll
        for (int j = 0; j < 4; j++) {
            int k = kt + sub + (j << 3);
            bool valid = (k <= q) && (k > q - WIN_);
            if (!valid) sc[j] = -INFINITY;
        }

        // ---- online softmax (reduce across the 8 lanes of this row)
        float mt = fmaxf(fmaxf(sc[0], sc[1]), fmaxf(sc[2], sc[3]));
        mt = fmaxf(mt, __shfl_xor_sync(0xffffffffu, mt, 1));
        mt = fmaxf(mt, __shfl_xor_sync(0xffffffffu, mt, 2));
        mt = fmaxf(mt, __shfl_xor_sync(0xffffffffu, mt, 4));
        float mnew = fmaxf(m, mt);

        float alpha, p[4];
        if (mnew == -INFINITY) {    // tile fully masked for this row
            alpha = 1.f;
            p[0] = p[1] = p[2] = p[3] = 0.f;
        } else {
            alpha = __expf(m - mnew);            // m=-inf -> 0
            #pragma unroll
            for (int j = 0; j < 4; j++)
                p[j] = __expf(sc[j] - mnew);     // sc=-inf -> 0
        }
        float psum = p[0] + p[1] + p[2] + p[3];
        psum += __shfl_xor_sync(0xffffffffu, psum, 1);
        psum += __shfl_xor_sync(0xffffffffu, psum, 2);
        psum += __shfl_xor_sync(0xffffffffu, psum, 4);
        l = l * alpha + psum;
        m = mnew;

        #pragma unroll
        for (int d = 0; d < 32; d++) acc[d] *= alpha;

        Ps[r*33 + sub     ] = p[0];
        Ps[r*33 + sub +  8] = p[1];
        Ps[r*33 + sub + 16] = p[2];
        Ps[r*33 + sub + 24] = p[3];
        __syncwarp();   // Ps row written & read entirely within this warp

        // ---- P @ V : this thread owns output dims d = sub + 8*dd
        #pragma unroll 4
        for (int kk = 0; kk < 32; kk++) {
            float pk = Ps[r*33 + kk];
            const float* vr = Vs + kk*257 + sub;
            #pragma unroll
            for (int dd = 0; dd < 32; dd++)
                acc[dd] += pk * vr[dd << 3];
        }
    }

    float invl = 1.f / l;
    int obase = ((b*S_ + q) * H_ + h) * HD_ + sub;
    #pragma unroll
    for (int dd = 0; dd < 32; dd++)
        g_attn[obase + (dd << 3)] = acc[dd] * invl;
}

// ---------------------------------------------------------------------------
extern "C" void kernel_launch(void* const* d_in, const int* in_sizes, int n_in,
                              void* d_out, int out_size)
{
    (void)in_sizes; (void)n_in; (void)out_size;
    const float* hidden = (const float*)d_in[0];
    // d_in[1] = attention_mask (pure causal; reproduced analytically)
    const int*   pos    = (const int*)  d_in[2];
    const float* Wq     = (const float*)d_in[3];
    const float* Wk     = (const float*)d_in[4];
    const float* Wv     = (const float*)d_in[5];
    const float* Wo     = (const float*)d_in[6];
    float* out = (float*)d_out;

    float *q, *k, *v, *attn;
    cudaGetSymbolAddress((void**)&q,    g_q);
    cudaGetSymbolAddress((void**)&k,    g_k);
    cudaGetSymbolAddress((void**)&v,    g_v);
    cudaGetSymbolAddress((void**)&attn, g_attn);

    dim3 blk(256);
    // QKV projections
    sgemm_nt<<<dim3(16, 32), blk>>>(hidden, Wq, q, B_*S_, H_*HD_, D_);
    sgemm_nt<<<dim3( 2, 32), blk>>>(hidden, Wk, k, B_*S_, HD_,    D_);
    sgemm_nt<<<dim3( 2, 32), blk>>>(hidden, Wv, v, B_*S_, HD_,    D_);
    // RoPE in place
    rope_kernel<<<B_*S_, 128>>>(pos);
    // Attention
    size_t smem = (size_t)(3*32*257 + 32*33) * sizeof(float);
    cudaFuncSetAttribute(attn_kernel,
                         cudaFuncAttributeMaxDynamicSharedMemorySize, (int)smem);
    attn_kernel<<<dim3(S_/32, B_*H_), 256, smem>>>();
    // Output projection
    sgemm_nt<<<dim3(16, 32), blk>>>(attn, Wo, out, B_*S_, D_, H_*HD_);
}